// round 8
// baseline (speedup 1.0000x reference)
#include <cuda_runtime.h>
#include <cstdint>

// Problem constants
#define BB   2048
#define LL   128

// Output layout (concatenated, float32)
#define OFF_PUZZ  33554432
#define OFF_FEAT  35397632
#define OFF_QST   153362432
#define OFF_LOSS  271327232

// Scratch
__device__ float g_partial[BB];
__device__ int   g_codes[BB * 30];
__device__ float g_enc[BB * 30 * 64];

// Pre-transposed weights
#define GW_W1T   0
#define GW_W2T   6336
#define GW_W3T   19008
#define GW_DW1T  31680
#define GW_DW2T  44352
#define GW_DW3T  61248
#define GW_OWT   69952
__device__ float g_wt[74176];

__global__ void prep_kernel(const float* __restrict__ w1, const float* __restrict__ w2,
                            const float* __restrict__ w3, const float* __restrict__ dw1,
                            const float* __restrict__ dw2, const float* __restrict__ dw3,
                            const float* __restrict__ ow)
{
    const int tid = blockIdx.x * blockDim.x + threadIdx.x;
    const int nt  = gridDim.x * blockDim.x;
    for (int i = tid; i < 6144; i += nt) {
        int o = i / 96, r = i - o * 96;
        g_wt[GW_W1T + r * 66 + o] = w1[i];
    }
    for (int i = tid; i < 12288; i += nt) {
        int o = i / 192, r = i - o * 192;
        g_wt[GW_W2T + r * 66 + o] = w2[i];
    }
    for (int i = tid; i < 12288; i += nt) {
        int o = i / 192, r = i - o * 192;
        g_wt[GW_W3T + r * 66 + o] = w3[i];
    }
    for (int i = tid; i < 12288; i += nt) {
        int q = i >> 6, o = i & 63;
        g_wt[GW_DW1T + q * 66 + o] = dw1[(q / 3) * 192 + o * 3 + (q % 3)];
    }
    for (int i = tid; i < 16384; i += nt) {
        int q = i >> 6, o = i & 63;
        g_wt[GW_DW2T + q * 66 + o] = dw2[(q >> 2) * 256 + o * 4 + (q & 3)];
    }
    for (int i = tid; i < 8192; i += nt) {
        int q = i >> 5, o = i & 31;
        g_wt[GW_DW3T + q * 34 + o] = dw3[(q >> 2) * 128 + o * 4 + (q & 3)];
    }
    for (int i = tid; i < 4096; i += nt) {
        int v = i >> 5, e = i & 31;
        g_wt[GW_OWT + e * 132 + v] = ow[i];
    }
}

// ---------------- Encoder shared layout (floats) ----------------
#define E_A     0
#define E_H2    0
#define E_ENC   2048
#define E_H1    4224
#define E_WT    8576
#define E_CB    12928
#define E_DIST  13568
#define E_BS    13872
#define E_FLOATS 13936
#define E_BYTES  (E_FLOATS * 4)

__global__ void __launch_bounds__(256, 4)
enc_kernel(const int* __restrict__ ti, const float* __restrict__ emb,
           const float* __restrict__ b1, const float* __restrict__ b2,
           const float* __restrict__ b3, const float* __restrict__ cb)
{
    extern __shared__ float s[];
    float* X   = s + E_A;
    float* H1  = s + E_H1;
    float* WT  = s + E_WT;
    float* CB  = s + E_CB;
    float* DIST= s + E_DIST;
    float* BS  = s + E_BS;
    float* H2  = s + E_A + E_H2;
    float* ENC = s + E_A + E_ENC;
    __shared__ int   codes_s[30];
    __shared__ float mind_s[30];

    const int tid = threadIdx.x;
    const int b   = blockIdx.x;

    for (int i = tid; i < 4224; i += 256) X[i] = 0.f;
    for (int i = tid; i < 4352; i += 256) H1[i] = 0.f;
    for (int i = tid; i < 640; i += 256) CB[i] = cb[i];
    if (tid < 64) BS[tid] = b1[tid];
    __syncthreads();

    // gather: X[e][l+1] = emb[ti[l]*32 + e]
    const int* tirow = ti + b * LL;
    for (int i = tid; i < LL * 32; i += 256) {
        int l = i >> 5, e = i & 31;
        X[e * 132 + l + 1] = emb[tirow[l] * 32 + e];
    }

    // conv1: X [32][128] pad1 s2 k3 -> H1 [64][64], ReLU.  2o x 8t, chunks of 16 e
    {
        const int o0 = (tid & 31) * 2;
        const int t0 = (tid >> 5) * 8;
        float acc0[8], acc1[8];
        #pragma unroll
        for (int ch = 0; ch < 2; ch++) {
            __syncthreads();
            const float4* src = (const float4*)(g_wt + GW_W1T + ch * 3168);
            for (int i = tid; i < 792; i += 256) ((float4*)WT)[i] = src[i];
            __syncthreads();
            if (ch == 0) {
                float bb0 = BS[o0], bb1 = BS[o0 + 1];
                #pragma unroll
                for (int u = 0; u < 8; u++) { acc0[u] = bb0; acc1[u] = bb1; }
            }
            for (int el = 0; el < 16; el++) {
                float xv[17];
                const float* xr = &X[(ch * 16 + el) * 132 + 2 * t0];
                #pragma unroll
                for (int u = 0; u < 4; u++) {
                    float4 v = *(const float4*)(xr + 4 * u);
                    xv[4*u] = v.x; xv[4*u+1] = v.y; xv[4*u+2] = v.z; xv[4*u+3] = v.w;
                }
                xv[16] = xr[16];
                #pragma unroll
                for (int k = 0; k < 3; k++) {
                    float2 w = *(const float2*)&WT[(el * 3 + k) * 66 + o0];
                    #pragma unroll
                    for (int t = 0; t < 8; t++) {
                        float x = xv[2 * t + k];
                        acc0[t] += w.x * x;
                        acc1[t] += w.y * x;
                    }
                }
            }
        }
        __syncthreads();
        #pragma unroll
        for (int t = 0; t < 8; t++) {
            H1[o0 * 68 + t0 + t + 1]       = fmaxf(acc0[t], 0.f);
            H1[(o0 + 1) * 68 + t0 + t + 1] = fmaxf(acc1[t], 0.f);
        }
    }
    __syncthreads();

    // conv2: H1 [64][64] pad1 s2 k3 -> H2 [64][32], ReLU.  2o x 4t, chunks of 16 e
    {
        const int o0 = (tid & 31) * 2;
        const int t0 = (tid >> 5) * 4;
        float acc0[4], acc1[4];
        #pragma unroll
        for (int ch = 0; ch < 4; ch++) {
            __syncthreads();
            const float4* src = (const float4*)(g_wt + GW_W2T + ch * 3168);
            for (int i = tid; i < 792; i += 256) ((float4*)WT)[i] = src[i];
            if (ch == 0 && tid < 64) BS[tid] = b2[tid];
            __syncthreads();
            if (ch == 0) {
                float bb0 = BS[o0], bb1 = BS[o0 + 1];
                #pragma unroll
                for (int u = 0; u < 4; u++) { acc0[u] = bb0; acc1[u] = bb1; }
            }
            for (int el = 0; el < 16; el++) {
                float xv[9];
                const float* xr = &H1[(ch * 16 + el) * 68 + 2 * t0];
                #pragma unroll
                for (int u = 0; u < 2; u++) {
                    float4 v = *(const float4*)(xr + 4 * u);
                    xv[4*u] = v.x; xv[4*u+1] = v.y; xv[4*u+2] = v.z; xv[4*u+3] = v.w;
                }
                xv[8] = xr[8];
                #pragma unroll
                for (int k = 0; k < 3; k++) {
                    float2 w = *(const float2*)&WT[(el * 3 + k) * 66 + o0];
                    #pragma unroll
                    for (int t = 0; t < 4; t++) {
                        float x = xv[2 * t + k];
                        acc0[t] += w.x * x;
                        acc1[t] += w.y * x;
                    }
                }
            }
        }
        __syncthreads();
        #pragma unroll
        for (int t = 0; t < 4; t++) {
            H2[o0 * 32 + t0 + t]       = fmaxf(acc0[t], 0.f);
            H2[(o0 + 1) * 32 + t0 + t] = fmaxf(acc1[t], 0.f);
        }
    }
    __syncthreads();

    // conv3: H2 [64][32] pad0 s1 k3 -> ENC [30][64] transposed.  2o x 5t, 192 act
    {
        const bool act = tid < 192;
        const int o0 = (tid & 31) * 2;
        const int t0 = (tid >> 5) * 5;
        float acc0[5], acc1[5];
        #pragma unroll
        for (int ch = 0; ch < 4; ch++) {
            __syncthreads();
            const float4* src = (const float4*)(g_wt + GW_W3T + ch * 3168);
            for (int i = tid; i < 792; i += 256) ((float4*)WT)[i] = src[i];
            if (ch == 0 && tid < 64) BS[tid] = b3[tid];
            __syncthreads();
            if (act) {
                if (ch == 0) {
                    float bb0 = BS[o0], bb1 = BS[o0 + 1];
                    #pragma unroll
                    for (int u = 0; u < 5; u++) { acc0[u] = bb0; acc1[u] = bb1; }
                }
                for (int el = 0; el < 16; el++) {
                    float xv[7];
                    const float* xr = &H2[(ch * 16 + el) * 32 + t0];
                    #pragma unroll
                    for (int u = 0; u < 7; u++) xv[u] = xr[u];
                    #pragma unroll
                    for (int k = 0; k < 3; k++) {
                        float2 w = *(const float2*)&WT[(el * 3 + k) * 66 + o0];
                        #pragma unroll
                        for (int t = 0; t < 5; t++) {
                            float x = xv[t + k];
                            acc0[t] += w.x * x;
                            acc1[t] += w.y * x;
                        }
                    }
                }
            }
        }
        __syncthreads();
        if (act) {
            #pragma unroll
            for (int t = 0; t < 5; t++) {
                ENC[(t0 + t) * 64 + o0]     = acc0[t];
                ENC[(t0 + t) * 64 + o0 + 1] = acc1[t];
            }
        }
    }
    __syncthreads();

    // VQ distances + argmin
    for (int idx = tid; idx < 300; idx += 256) {
        int i = idx / 10, c = idx - i * 10;
        const float* fe = &ENC[i * 64];
        const float* cc = &CB[c * 64];
        float acc = 0.f;
        #pragma unroll 8
        for (int d = 0; d < 64; d++) { float df = fe[d] - cc[d]; acc += df * df; }
        DIST[i * 10 + c] = acc;
    }
    __syncthreads();
    if (tid < 30) {
        float mv = DIST[tid * 10]; int mc = 0;
        #pragma unroll
        for (int c = 1; c < 10; c++) {
            float v = DIST[tid * 10 + c];
            if (v < mv) { mv = v; mc = c; }
        }
        codes_s[tid] = mc;
        mind_s[tid] = mv;
        g_codes[b * 30 + tid] = mc;
    }
    __syncthreads();
    if (tid == 0) {
        float acc = 0.f;
        #pragma unroll
        for (int i = 0; i < 30; i++) acc += mind_s[i];
        g_partial[b] = acc;
    }

    // write ENC rows to scratch (coalesced float4)
    {
        float4* dst = (float4*)g_enc + (size_t)b * 480;
        const float4* src = (const float4*)ENC;
        for (int i = tid; i < 480; i += 256) dst[i] = src[i];
    }
}

// ---------------- Broadcast fill (no smem, no barriers) ----------------
__global__ void __launch_bounds__(256)
fill_kernel(const float* __restrict__ cb,
            float* __restrict__ out_feat, float* __restrict__ out_qst,
            float* __restrict__ out_puzz)
{
    const int b   = blockIdx.x;
    const int tid = threadIdx.x;
    const int lane = tid & 31;
    const int wid  = tid >> 5;
    const int q    = lane & 15;
    const int jh   = lane >> 4;

    const int* codes = g_codes + b * 30;
    float* pz = out_puzz + (size_t)b * 900;
    for (int idx = tid; idx < 900; idx += 256)
        __stcs(&pz[idx], (float)__ldg(&codes[idx / 30]));

    const float4* enc4 = (const float4*)g_enc + (size_t)b * 480;
    const float4* cb4  = (const float4*)cb;
    float4* f4 = (float4*)out_feat + (size_t)b * 14400;
    float4* q4 = (float4*)out_qst  + (size_t)b * 14400;
    for (int i = wid; i < 30; i += 8) {
        float4 ev = __ldg(&enc4[i * 16 + q]);
        int code  = __ldg(&codes[i]);
        float4 cv = __ldg(&cb4[code * 16 + q]);
        float4* fb = f4 + i * 480 + jh * 16 + q;
        float4* qb = q4 + i * 480 + jh * 16 + q;
        #pragma unroll
        for (int j = 0; j < 30; j += 2) {
            __stcs(fb + j * 16, ev);
            __stcs(qb + j * 16, cv);
        }
    }
}

// ---------------- Decoder shared layout (floats) ----------------
#define D_A     0
#define D_F     0
#define D_G1    2304
#define D_G3    0
#define D_G2    4608
#define D_WT    8960
#define D_CB    13312
#define D_BS    13952
#define D_OB    14016
#define D_FLOATS 14144
#define D_BYTES  (D_FLOATS * 4)

__global__ void __launch_bounds__(256, 4)
dec_kernel(const float* __restrict__ cb,
           const float* __restrict__ db1, const float* __restrict__ db2,
           const float* __restrict__ db3, const float* __restrict__ ob,
           float* __restrict__ out_logits)
{
    extern __shared__ float s[];
    float* F  = s + D_F;
    float* G1 = s + D_G1;
    float* G2 = s + D_G2;
    float* G3 = s + D_G3;
    float* WT = s + D_WT;
    float* CB = s + D_CB;
    float* BS = s + D_BS;
    float* OB = s + D_OB;
    __shared__ int codes_s[30];

    const int tid = threadIdx.x;
    const int b   = blockIdx.x;

    for (int i = tid; i < 4608; i += 256) s[D_A + i] = 0.f;
    for (int i = tid; i < 4352; i += 256) G2[i] = 0.f;
    for (int i = tid; i < 640; i += 256) CB[i] = cb[i];
    if (tid < 30) codes_s[tid] = g_codes[b * 30 + tid];
    if (tid < 64) BS[tid] = db1[tid];
    __syncthreads();

    // F[d][i+2] = codebook[code[i]][d]
    for (int idx = tid; idx < 64 * 30; idx += 256) {
        int d = idx / 30, i = idx - d * 30;
        F[d * 36 + i + 2] = CB[codes_s[i] * 64 + d];
    }

    // convT1: F [64][30] s1 p0 k3 -> G1 [64][32], ReLU.  2o x 4t, chunks of 16 cl
    {
        const int o0 = (tid & 31) * 2;
        const int t0 = (tid >> 5) * 4;
        float ac0[4], ac1[4];
        {
            float bb0 = BS[o0], bb1 = BS[o0 + 1];
            #pragma unroll
            for (int u = 0; u < 4; u++) { ac0[u] = bb0; ac1[u] = bb1; }
        }
        #pragma unroll
        for (int ch = 0; ch < 4; ch++) {
            __syncthreads();
            const float4* src = (const float4*)(g_wt + GW_DW1T + ch * 3168);
            for (int i = tid; i < 792; i += 256) ((float4*)WT)[i] = src[i];
            __syncthreads();
            for (int cl = 0; cl < 16; cl++) {
                float xv[6];
                const float* xr = &F[(ch * 16 + cl) * 36 + t0];
                {
                    float4 v = *(const float4*)xr;
                    float2 v2 = *(const float2*)(xr + 4);
                    xv[0]=v.x; xv[1]=v.y; xv[2]=v.z; xv[3]=v.w; xv[4]=v2.x; xv[5]=v2.y;
                }
                #pragma unroll
                for (int k = 0; k < 3; k++) {
                    float2 w = *(const float2*)&WT[(cl * 3 + k) * 66 + o0];
                    #pragma unroll
                    for (int t = 0; t < 4; t++) {
                        float x = xv[t + 2 - k];
                        ac0[t] += w.x * x;
                        ac1[t] += w.y * x;
                    }
                }
            }
        }
        __syncthreads();
        #pragma unroll
        for (int t = 0; t < 4; t++) {
            G1[o0 * 36 + t0 + t + 1]       = fmaxf(ac0[t], 0.f);
            G1[(o0 + 1) * 36 + t0 + t + 1] = fmaxf(ac1[t], 0.f);
        }
    }
    __syncthreads();

    // convT2: G1 [64][32] s2 p1 k4 -> G2 [64][64], ReLU.  2o x 8t, chunks of 16 cl
    {
        const int oo = (tid & 31) * 2;
        const int tt0 = (tid >> 5) * 8;
        float b20[8], b21[8];
        if (tid < 64) BS[tid] = db2[tid];
        __syncthreads();
        {
            float bb0 = BS[oo], bb1 = BS[oo + 1];
            #pragma unroll
            for (int u = 0; u < 8; u++) { b20[u] = bb0; b21[u] = bb1; }
        }
        #pragma unroll
        for (int ch = 0; ch < 4; ch++) {
            __syncthreads();
            const float4* src = (const float4*)(g_wt + GW_DW2T + ch * 4224);
            for (int i = tid; i < 1056; i += 256) ((float4*)WT)[i] = src[i];
            __syncthreads();
            for (int cl = 0; cl < 16; cl++) {
                float xv[6];
                const float* xr = &G1[(ch * 16 + cl) * 36 + (tt0 >> 1)];
                {
                    float4 v = *(const float4*)xr;
                    float2 v2 = *(const float2*)(xr + 4);
                    xv[0]=v.x; xv[1]=v.y; xv[2]=v.z; xv[3]=v.w; xv[4]=v2.x; xv[5]=v2.y;
                }
                float2 w0 = *(const float2*)&WT[(cl * 4 + 0) * 66 + oo];
                float2 w1 = *(const float2*)&WT[(cl * 4 + 1) * 66 + oo];
                float2 w2 = *(const float2*)&WT[(cl * 4 + 2) * 66 + oo];
                float2 w3 = *(const float2*)&WT[(cl * 4 + 3) * 66 + oo];
                #pragma unroll
                for (int t = 0; t < 8; t++) {
                    int u1 = ((t + 1) >> 1) + 1;
                    float xh = xv[u1], xl = xv[u1 - 1];
                    if (t & 1) {
                        b20[t] += w0.x * xh + w2.x * xl;
                        b21[t] += w0.y * xh + w2.y * xl;
                    } else {
                        b20[t] += w1.x * xh + w3.x * xl;
                        b21[t] += w1.y * xh + w3.y * xl;
                    }
                }
            }
        }
        __syncthreads();
        #pragma unroll
        for (int t = 0; t < 8; t++) {
            G2[oo * 68 + tt0 + t + 1]       = fmaxf(b20[t], 0.f);
            G2[(oo + 1) * 68 + tt0 + t + 1] = fmaxf(b21[t], 0.f);
        }
    }
    __syncthreads();

    // convT3: G2 [64][64] s2 p1 k4 -> G3 [32][128].  2o x 8t, chunks of 32 c
    {
        const int oo = (tid & 15) * 2;
        const int tt0 = (tid >> 4) * 8;
        float b30[8], b31[8];
        if (tid < 32) BS[tid] = db3[tid];
        __syncthreads();
        {
            float bb0 = BS[oo], bb1 = BS[oo + 1];
            #pragma unroll
            for (int u = 0; u < 8; u++) { b30[u] = bb0; b31[u] = bb1; }
        }
        #pragma unroll
        for (int ch = 0; ch < 2; ch++) {
            __syncthreads();
            const float4* src = (const float4*)(g_wt + GW_DW3T + ch * 4352);
            for (int i = tid; i < 1088; i += 256) ((float4*)WT)[i] = src[i];
            __syncthreads();
            for (int cl = 0; cl < 32; cl++) {
                float xv[6];
                const float* xr = &G2[(ch * 32 + cl) * 68 + (tt0 >> 1)];
                {
                    float4 v = *(const float4*)xr;
                    float2 v2 = *(const float2*)(xr + 4);
                    xv[0]=v.x; xv[1]=v.y; xv[2]=v.z; xv[3]=v.w; xv[4]=v2.x; xv[5]=v2.y;
                }
                float2 w0 = *(const float2*)&WT[(cl * 4 + 0) * 34 + oo];
                float2 w1 = *(const float2*)&WT[(cl * 4 + 1) * 34 + oo];
                float2 w2 = *(const float2*)&WT[(cl * 4 + 2) * 34 + oo];
                float2 w3 = *(const float2*)&WT[(cl * 4 + 3) * 34 + oo];
                #pragma unroll
                for (int t = 0; t < 8; t++) {
                    int u1 = ((t + 1) >> 1) + 1;
                    float xh = xv[u1], xl = xv[u1 - 1];
                    if (t & 1) {
                        b30[t] += w0.x * xh + w2.x * xl;
                        b31[t] += w0.y * xh + w2.y * xl;
                    } else {
                        b30[t] += w1.x * xh + w3.x * xl;
                        b31[t] += w1.y * xh + w3.y * xl;
                    }
                }
            }
        }
        __syncthreads();
        #pragma unroll
        for (int t = 0; t < 8; t++) {
            G3[oo * 132 + tt0 + t]       = b30[t];
            G3[(oo + 1) * 132 + tt0 + t] = b31[t];
        }
    }
    __syncthreads();

    // final GEMM: 4v x 8l, two l-passes
    {
        const float4* src = (const float4*)(g_wt + GW_OWT);
        for (int i = tid; i < 1056; i += 256) ((float4*)WT)[i] = src[i];
        if (tid < 128) OB[tid] = ob[tid];
        __syncthreads();
        const int v0 = (tid & 31) * 4;
        const int l0 = (tid >> 5) * 16;
        #pragma unroll
        for (int lh = 0; lh < 2; lh++) {
            const int l = l0 + lh * 8;
            float ga[4][8];
            #pragma unroll
            for (int j = 0; j < 4; j++) {
                float bj = OB[v0 + j];
                #pragma unroll
                for (int u = 0; u < 8; u++) ga[j][u] = bj;
            }
            for (int e = 0; e < 32; e++) {
                float xv[8];
                const float* xr = &G3[e * 132 + l];
                #pragma unroll
                for (int u = 0; u < 2; u++) {
                    float4 v = *(const float4*)(xr + 4 * u);
                    xv[4*u] = v.x; xv[4*u+1] = v.y; xv[4*u+2] = v.z; xv[4*u+3] = v.w;
                }
                float4 w = *(const float4*)&WT[e * 132 + v0];
                #pragma unroll
                for (int u = 0; u < 8; u++) {
                    float x = xv[u];
                    ga[0][u] += w.x * x;
                    ga[1][u] += w.y * x;
                    ga[2][u] += w.z * x;
                    ga[3][u] += w.w * x;
                }
            }
            float* outp = out_logits + ((size_t)b * 128 + l) * 128 + v0;
            #pragma unroll
            for (int u = 0; u < 8; u++) {
                float4 vv = make_float4(ga[0][u], ga[1][u], ga[2][u], ga[3][u]);
                __stcs((float4*)(outp + (size_t)u * 128), vv);
            }
        }
    }
}

// Deterministic loss reduce
__global__ void loss_kernel(float* __restrict__ out_loss)
{
    __shared__ float sm[256];
    float a = 0.f;
    for (int i = threadIdx.x; i < BB; i += 256) a += g_partial[i];
    sm[threadIdx.x] = a;
    __syncthreads();
    for (int sft = 128; sft > 0; sft >>= 1) {
        if (threadIdx.x < sft) sm[threadIdx.x] += sm[threadIdx.x + sft];
        __syncthreads();
    }
    if (threadIdx.x == 0)
        out_loss[0] = sm[0] * (1.25f / (2048.f * 30.f * 64.f));
}

extern "C" void kernel_launch(void* const* d_in, const int* in_sizes, int n_in,
                              void* d_out, int out_size)
{
    const int*   ti     = (const int*)  d_in[0];
    const float* emb    = (const float*)d_in[1];
    const float* enc_w1 = (const float*)d_in[2];
    const float* enc_b1 = (const float*)d_in[3];
    const float* enc_w2 = (const float*)d_in[4];
    const float* enc_b2 = (const float*)d_in[5];
    const float* enc_w3 = (const float*)d_in[6];
    const float* enc_b3 = (const float*)d_in[7];
    const float* cb     = (const float*)d_in[8];
    const float* dec_w1 = (const float*)d_in[9];
    const float* dec_b1 = (const float*)d_in[10];
    const float* dec_w2 = (const float*)d_in[11];
    const float* dec_b2 = (const float*)d_in[12];
    const float* dec_w3 = (const float*)d_in[13];
    const float* dec_b3 = (const float*)d_in[14];
    const float* out_w  = (const float*)d_in[15];
    const float* out_b  = (const float*)d_in[16];

    float* out        = (float*)d_out;
    float* out_logits = out;
    float* out_puzz   = out + OFF_PUZZ;
    float* out_feat   = out + OFF_FEAT;
    float* out_qst    = out + OFF_QST;
    float* out_loss   = out + OFF_LOSS;

    static cudaStream_t s2 = nullptr;
    static cudaEvent_t evA = nullptr, evB = nullptr;
    if (s2 == nullptr) {
        cudaStreamCreateWithFlags(&s2, cudaStreamNonBlocking);
        cudaEventCreateWithFlags(&evA, cudaEventDisableTiming);
        cudaEventCreateWithFlags(&evB, cudaEventDisableTiming);
    }

    cudaFuncSetAttribute(enc_kernel, cudaFuncAttributeMaxDynamicSharedMemorySize, E_BYTES);
    cudaFuncSetAttribute(dec_kernel, cudaFuncAttributeMaxDynamicSharedMemorySize, D_BYTES);

    // main stream: prep -> enc -> dec
    prep_kernel<<<64, 256>>>(enc_w1, enc_w2, enc_w3, dec_w1, dec_w2, dec_w3, out_w);
    enc_kernel<<<BB, 256, E_BYTES>>>(ti, emb, enc_b1, enc_b2, enc_b3, cb);

    // fork: fill + loss run concurrently with dec
    cudaEventRecord(evA, 0);
    cudaStreamWaitEvent(s2, evA, 0);
    fill_kernel<<<BB, 256, 0, s2>>>(cb, out_feat, out_qst, out_puzz);
    loss_kernel<<<1, 256, 0, s2>>>(out_loss);
    cudaEventRecord(evB, s2);

    dec_kernel<<<BB, 256, D_BYTES>>>(cb, dec_b1, dec_b2, dec_b3, out_b, out_logits);

    // join
    cudaStreamWaitEvent(0, evB, 0);
}

// round 9
// speedup vs baseline: 1.1015x; 1.1015x over previous
#include <cuda_runtime.h>
#include <cstdint>

typedef unsigned long long u64;

__device__ __forceinline__ u64 pk(float x) {
    u64 r; asm("mov.b64 %0, {%1, %1};" : "=l"(r) : "f"(x)); return r;
}
__device__ __forceinline__ u64 pk2(float x, float y) {
    u64 r; asm("mov.b64 %0, {%1, %2};" : "=l"(r) : "f"(x), "f"(y)); return r;
}
__device__ __forceinline__ void fma2(u64& d, u64 a, u64 b) {
    asm("fma.rn.f32x2 %0, %1, %2, %0;" : "+l"(d) : "l"(a), "l"(b));
}
__device__ __forceinline__ float2 upk(u64 v) {
    float2 r; asm("mov.b64 {%0, %1}, %2;" : "=f"(r.x), "=f"(r.y) : "l"(v)); return r;
}

// Problem constants
#define BB   2048
#define LL   128

// Output layout (concatenated, float32)
#define OFF_PUZZ  33554432
#define OFF_FEAT  35397632
#define OFF_QST   153362432
#define OFF_LOSS  271327232

// Scratch
__device__ float g_partial[BB];

// Pre-transposed weights (stride-68 rows for float4-aligned o-major access)
#define GW_W1T   0
#define GW_W2T   6528
#define GW_W3T   19584
#define GW_DW1T  32640
#define GW_DW2T  45696
#define GW_DW3T  63104
#define GW_OWT   71808
__device__ __align__(16) float g_wt[76032];

__global__ void prep_kernel(const float* __restrict__ w1, const float* __restrict__ w2,
                            const float* __restrict__ w3, const float* __restrict__ dw1,
                            const float* __restrict__ dw2, const float* __restrict__ dw3,
                            const float* __restrict__ ow)
{
    const int tid = blockIdx.x * blockDim.x + threadIdx.x;
    const int nt  = gridDim.x * blockDim.x;
    for (int i = tid; i < 6144; i += nt) {
        int o = i / 96, r = i - o * 96;
        g_wt[GW_W1T + r * 68 + o] = w1[i];
    }
    for (int i = tid; i < 12288; i += nt) {
        int o = i / 192, r = i - o * 192;
        g_wt[GW_W2T + r * 68 + o] = w2[i];
    }
    for (int i = tid; i < 12288; i += nt) {
        int o = i / 192, r = i - o * 192;
        g_wt[GW_W3T + r * 68 + o] = w3[i];
    }
    for (int i = tid; i < 12288; i += nt) {
        int q = i >> 6, o = i & 63;
        g_wt[GW_DW1T + q * 68 + o] = dw1[(q / 3) * 192 + o * 3 + (q % 3)];
    }
    for (int i = tid; i < 16384; i += nt) {
        int q = i >> 6, o = i & 63;
        g_wt[GW_DW2T + q * 68 + o] = dw2[(q >> 2) * 256 + o * 4 + (q & 3)];
    }
    for (int i = tid; i < 8192; i += nt) {
        int q = i >> 5, o = i & 31;
        g_wt[GW_DW3T + q * 34 + o] = dw3[(q >> 2) * 128 + o * 4 + (q & 3)];
    }
    for (int i = tid; i < 4096; i += nt) {
        int v = i >> 5, e = i & 31;
        g_wt[GW_OWT + e * 132 + v] = ow[i];
    }
}

// ---------------- Fused shared layout (floats) ----------------
// A  (4608) @0     : enc: X[32][132](4224) -> H2[64][34]@0 + ENC[30][64]@2176
//                    dec: F[64][36]@0 + G1[64][36]@2304 -> G3[32][132]@0
// B  (4352) @4608  : enc: H1[64][68]   dec: G2[64][68]
// WT (4352) @8960 ; CB (640) @13312 ; DIST(304) @13952 ; BS(64) @14256 ; OB(128) @14320
#define SM_A     0
#define SM_B     4608
#define SM_WT    8960
#define SM_CB    13312
#define SM_DIST  13952
#define SM_BS    14256
#define SM_OB    14320
#define SM_FLOATS 14448
#define SM_BYTES  (SM_FLOATS * 4)

#define A_H2   0
#define A_ENC  2176
#define A_F    0
#define A_G1   2304
#define A_G3   0

__global__ void __launch_bounds__(256, 4)
fused_kernel(const int* __restrict__ ti, const float* __restrict__ emb,
             const float* __restrict__ b1, const float* __restrict__ b2,
             const float* __restrict__ b3, const float* __restrict__ cb,
             const float* __restrict__ db1, const float* __restrict__ db2,
             const float* __restrict__ db3, const float* __restrict__ ob,
             float* __restrict__ out_logits,
             float* __restrict__ out_feat, float* __restrict__ out_qst,
             float* __restrict__ out_puzz)
{
    extern __shared__ float s[];
    float* X   = s + SM_A;
    float* H1  = s + SM_B;
    float* WT  = s + SM_WT;
    float* CB  = s + SM_CB;
    float* DIST= s + SM_DIST;
    float* BS  = s + SM_BS;
    float* OB  = s + SM_OB;
    float* H2  = s + SM_A + A_H2;
    float* ENC = s + SM_A + A_ENC;
    float* F   = s + SM_A + A_F;
    float* G1  = s + SM_A + A_G1;
    float* G2  = s + SM_B;
    float* G3  = s + SM_A + A_G3;
    __shared__ int   codes_s[30];
    __shared__ float mind_s[30];

    const int tid = threadIdx.x;
    const int b   = blockIdx.x;

    // ================= ENCODER =================
    for (int i = tid; i < 4224; i += 256) X[i] = 0.f;
    for (int i = tid; i < 4352; i += 256) H1[i] = 0.f;
    for (int i = tid; i < 640; i += 256) CB[i] = cb[i];
    if (tid < 64) BS[tid] = b1[tid];
    __syncthreads();

    // gather: X[e][l+1] = emb[ti[l]*32 + e]
    const int* tirow = ti + b * LL;
    for (int i = tid; i < LL * 32; i += 256) {
        int l = i >> 5, e = i & 31;
        X[e * 132 + l + 1] = emb[tirow[l] * 32 + e];
    }

    // conv1: X [32][128] pad1 s2 k3 -> H1 [64][64], ReLU.  4o x 4t, f32x2
    {
        const int o0 = (tid & 15) * 4;
        const int t0 = (tid >> 4) * 4;
        u64 a01[4], a23[4];
        #pragma unroll
        for (int ch = 0; ch < 2; ch++) {
            __syncthreads();
            const float4* src = (const float4*)(g_wt + GW_W1T + ch * 3264);
            for (int i = tid; i < 816; i += 256) ((float4*)WT)[i] = src[i];
            __syncthreads();
            if (ch == 0) {
                u64 bb01 = pk2(BS[o0], BS[o0 + 1]);
                u64 bb23 = pk2(BS[o0 + 2], BS[o0 + 3]);
                #pragma unroll
                for (int t = 0; t < 4; t++) { a01[t] = bb01; a23[t] = bb23; }
            }
            for (int el = 0; el < 16; el++) {
                const float* xr = &X[(ch * 16 + el) * 132 + 2 * t0];
                float4 v0 = *(const float4*)xr;
                float4 v1 = *(const float4*)(xr + 4);
                float x8 = xr[8];
                u64 xp[9];
                xp[0]=pk(v0.x); xp[1]=pk(v0.y); xp[2]=pk(v0.z); xp[3]=pk(v0.w);
                xp[4]=pk(v1.x); xp[5]=pk(v1.y); xp[6]=pk(v1.z); xp[7]=pk(v1.w);
                xp[8]=pk(x8);
                #pragma unroll
                for (int k = 0; k < 3; k++) {
                    const u64* wp = (const u64*)&WT[(el * 3 + k) * 68 + o0];
                    u64 w01 = wp[0], w23 = wp[1];
                    #pragma unroll
                    for (int t = 0; t < 4; t++) {
                        fma2(a01[t], w01, xp[2 * t + k]);
                        fma2(a23[t], w23, xp[2 * t + k]);
                    }
                }
            }
        }
        __syncthreads();
        #pragma unroll
        for (int t = 0; t < 4; t++) {
            float2 p01 = upk(a01[t]), p23 = upk(a23[t]);
            H1[(o0 + 0) * 68 + t0 + t + 1] = fmaxf(p01.x, 0.f);
            H1[(o0 + 1) * 68 + t0 + t + 1] = fmaxf(p01.y, 0.f);
            H1[(o0 + 2) * 68 + t0 + t + 1] = fmaxf(p23.x, 0.f);
            H1[(o0 + 3) * 68 + t0 + t + 1] = fmaxf(p23.y, 0.f);
        }
    }
    __syncthreads();

    // conv2: H1 [64][64] pad1 s2 k3 -> H2 [64][32] (stride 34), ReLU.  4o x 2t, f32x2
    {
        const int o0 = (tid & 15) * 4;
        const int t0 = (tid >> 4) * 2;
        u64 a01[2], a23[2];
        #pragma unroll
        for (int ch = 0; ch < 4; ch++) {
            __syncthreads();
            const float4* src = (const float4*)(g_wt + GW_W2T + ch * 3264);
            for (int i = tid; i < 816; i += 256) ((float4*)WT)[i] = src[i];
            if (ch == 0 && tid < 64) BS[tid] = b2[tid];
            __syncthreads();
            if (ch == 0) {
                u64 bb01 = pk2(BS[o0], BS[o0 + 1]);
                u64 bb23 = pk2(BS[o0 + 2], BS[o0 + 3]);
                a01[0] = a01[1] = bb01;
                a23[0] = a23[1] = bb23;
            }
            for (int el = 0; el < 16; el++) {
                const float* xr = &H1[(ch * 16 + el) * 68 + 2 * t0];
                float4 v = *(const float4*)xr;
                float x4 = xr[4];
                u64 xp[5];
                xp[0]=pk(v.x); xp[1]=pk(v.y); xp[2]=pk(v.z); xp[3]=pk(v.w); xp[4]=pk(x4);
                #pragma unroll
                for (int k = 0; k < 3; k++) {
                    const u64* wp = (const u64*)&WT[(el * 3 + k) * 68 + o0];
                    u64 w01 = wp[0], w23 = wp[1];
                    #pragma unroll
                    for (int t = 0; t < 2; t++) {
                        fma2(a01[t], w01, xp[2 * t + k]);
                        fma2(a23[t], w23, xp[2 * t + k]);
                    }
                }
            }
        }
        __syncthreads();
        #pragma unroll
        for (int t = 0; t < 2; t++) {
            float2 p01 = upk(a01[t]), p23 = upk(a23[t]);
            H2[(o0 + 0) * 34 + t0 + t] = fmaxf(p01.x, 0.f);
            H2[(o0 + 1) * 34 + t0 + t] = fmaxf(p01.y, 0.f);
            H2[(o0 + 2) * 34 + t0 + t] = fmaxf(p23.x, 0.f);
            H2[(o0 + 3) * 34 + t0 + t] = fmaxf(p23.y, 0.f);
        }
    }
    __syncthreads();

    // conv3: H2 [64][32] pad0 s1 k3 -> ENC [30][64] transposed.  2o x 5t, 192 act, f32x2
    {
        const bool act = tid < 192;
        const int o0 = (tid & 31) * 2;
        const int t0 = (tid >> 5) * 5;
        u64 ap[5];
        #pragma unroll
        for (int ch = 0; ch < 4; ch++) {
            __syncthreads();
            const float4* src = (const float4*)(g_wt + GW_W3T + ch * 3264);
            for (int i = tid; i < 816; i += 256) ((float4*)WT)[i] = src[i];
            if (ch == 0 && tid < 64) BS[tid] = b3[tid];
            __syncthreads();
            if (act) {
                if (ch == 0) {
                    u64 bb = pk2(BS[o0], BS[o0 + 1]);
                    #pragma unroll
                    for (int t = 0; t < 5; t++) ap[t] = bb;
                }
                for (int el = 0; el < 16; el++) {
                    const float* xr = &H2[(ch * 16 + el) * 34 + t0];
                    u64 xp[7];
                    #pragma unroll
                    for (int u = 0; u < 7; u++) xp[u] = pk(xr[u]);
                    #pragma unroll
                    for (int k = 0; k < 3; k++) {
                        u64 w = *(const u64*)&WT[(el * 3 + k) * 68 + o0];
                        #pragma unroll
                        for (int t = 0; t < 5; t++) fma2(ap[t], w, xp[t + k]);
                    }
                }
            }
        }
        __syncthreads();
        if (act) {
            #pragma unroll
            for (int t = 0; t < 5; t++) {
                float2 p = upk(ap[t]);
                ENC[(t0 + t) * 64 + o0]     = p.x;
                ENC[(t0 + t) * 64 + o0 + 1] = p.y;
            }
        }
    }
    __syncthreads();

    // VQ distances + argmin
    for (int idx = tid; idx < 300; idx += 256) {
        int i = idx / 10, c = idx - i * 10;
        const float* fe = &ENC[i * 64];
        const float* cc = &CB[c * 64];
        float acc = 0.f;
        #pragma unroll 8
        for (int d = 0; d < 64; d++) { float df = fe[d] - cc[d]; acc += df * df; }
        DIST[i * 10 + c] = acc;
    }
    __syncthreads();
    if (tid < 30) {
        float mv = DIST[tid * 10]; int mc = 0;
        #pragma unroll
        for (int c = 1; c < 10; c++) {
            float v = DIST[tid * 10 + c];
            if (v < mv) { mv = v; mc = c; }
        }
        codes_s[tid] = mc;
        mind_s[tid] = mv;
    }
    __syncthreads();
    if (tid == 0) {
        float acc = 0.f;
        #pragma unroll
        for (int i = 0; i < 30; i++) acc += mind_s[i];
        g_partial[b] = acc;
    }

    // ---- broadcast stores (register-cached, streaming); drain overlaps decoder ----
    {
        float* puz = out_puzz + (size_t)b * 900;
        for (int idx = tid; idx < 900; idx += 256)
            __stcs(&puz[idx], (float)codes_s[idx / 30]);

        const float4* enc4 = (const float4*)ENC;
        const float4* cb4  = (const float4*)CB;
        float4* f4 = (float4*)out_feat + (size_t)b * 14400;
        float4* q4 = (float4*)out_qst  + (size_t)b * 14400;
        const int lane = tid & 31;
        const int wid  = tid >> 5;
        const int q    = lane & 15;
        const int jh   = lane >> 4;
        for (int i = wid; i < 30; i += 8) {
            float4 ev = enc4[i * 16 + q];
            float4 cv = cb4[codes_s[i] * 16 + q];
            float4* fb = f4 + i * 480 + jh * 16 + q;
            float4* qb = q4 + i * 480 + jh * 16 + q;
            #pragma unroll
            for (int j = 0; j < 30; j += 2) {
                __stcs(fb + j * 16, ev);
                __stcs(qb + j * 16, cv);
            }
        }
    }
    __syncthreads();

    // ================= DECODER =================
    for (int i = tid; i < 4608; i += 256) s[SM_A + i] = 0.f;
    for (int i = tid; i < 4352; i += 256) G2[i] = 0.f;
    if (tid < 64) BS[tid] = db1[tid];
    __syncthreads();

    // F[d][i+2] = codebook[code[i]][d]
    for (int idx = tid; idx < 64 * 30; idx += 256) {
        int d = idx / 30, i = idx - d * 30;
        F[d * 36 + i + 2] = CB[codes_s[i] * 64 + d];
    }

    // convT1: F [64][30] s1 p0 k3 -> G1 [64][32], ReLU.  2o x 4t, f32x2
    {
        const int o0 = (tid & 31) * 2;
        const int t0 = (tid >> 5) * 4;
        u64 ap[4];
        {
            u64 bb = pk2(BS[o0], BS[o0 + 1]);
            #pragma unroll
            for (int t = 0; t < 4; t++) ap[t] = bb;
        }
        #pragma unroll
        for (int ch = 0; ch < 4; ch++) {
            __syncthreads();
            const float4* src = (const float4*)(g_wt + GW_DW1T + ch * 3264);
            for (int i = tid; i < 816; i += 256) ((float4*)WT)[i] = src[i];
            __syncthreads();
            for (int cl = 0; cl < 16; cl++) {
                const float* xr = &F[(ch * 16 + cl) * 36 + t0];
                float4 v = *(const float4*)xr;
                float2 v2 = *(const float2*)(xr + 4);
                u64 xp[6];
                xp[0]=pk(v.x); xp[1]=pk(v.y); xp[2]=pk(v.z); xp[3]=pk(v.w);
                xp[4]=pk(v2.x); xp[5]=pk(v2.y);
                #pragma unroll
                for (int k = 0; k < 3; k++) {
                    u64 w = *(const u64*)&WT[(cl * 3 + k) * 68 + o0];
                    #pragma unroll
                    for (int t = 0; t < 4; t++) fma2(ap[t], w, xp[t + 2 - k]);
                }
            }
        }
        __syncthreads();
        #pragma unroll
        for (int t = 0; t < 4; t++) {
            float2 p = upk(ap[t]);
            G1[o0 * 36 + t0 + t + 1]       = fmaxf(p.x, 0.f);
            G1[(o0 + 1) * 36 + t0 + t + 1] = fmaxf(p.y, 0.f);
        }
    }
    __syncthreads();

    // convT2: G1 [64][32] s2 p1 k4 -> G2 [64][64], ReLU.  2o x 8t, f32x2
    {
        const int oo = (tid & 31) * 2;
        const int tt0 = (tid >> 5) * 8;
        u64 ap[8];
        if (tid < 64) BS[tid] = db2[tid];
        __syncthreads();
        {
            u64 bb = pk2(BS[oo], BS[oo + 1]);
            #pragma unroll
            for (int t = 0; t < 8; t++) ap[t] = bb;
        }
        #pragma unroll
        for (int ch = 0; ch < 4; ch++) {
            __syncthreads();
            const float4* src = (const float4*)(g_wt + GW_DW2T + ch * 4352);
            for (int i = tid; i < 1088; i += 256) ((float4*)WT)[i] = src[i];
            __syncthreads();
            for (int cl = 0; cl < 16; cl++) {
                const float* xr = &G1[(ch * 16 + cl) * 36 + (tt0 >> 1)];
                float4 v = *(const float4*)xr;
                float2 v2 = *(const float2*)(xr + 4);
                u64 xp[6];
                xp[0]=pk(v.x); xp[1]=pk(v.y); xp[2]=pk(v.z); xp[3]=pk(v.w);
                xp[4]=pk(v2.x); xp[5]=pk(v2.y);
                const float* wb = &WT[(cl * 4) * 68 + oo];
                u64 w0 = *(const u64*)(wb);
                u64 w1 = *(const u64*)(wb + 68);
                u64 w2 = *(const u64*)(wb + 136);
                u64 w3 = *(const u64*)(wb + 204);
                #pragma unroll
                for (int t = 0; t < 8; t++) {
                    int u1 = ((t + 1) >> 1) + 1;
                    if (t & 1) {
                        fma2(ap[t], w0, xp[u1]);
                        fma2(ap[t], w2, xp[u1 - 1]);
                    } else {
                        fma2(ap[t], w1, xp[u1]);
                        fma2(ap[t], w3, xp[u1 - 1]);
                    }
                }
            }
        }
        __syncthreads();
        #pragma unroll
        for (int t = 0; t < 8; t++) {
            float2 p = upk(ap[t]);
            G2[oo * 68 + tt0 + t + 1]       = fmaxf(p.x, 0.f);
            G2[(oo + 1) * 68 + tt0 + t + 1] = fmaxf(p.y, 0.f);
        }
    }
    __syncthreads();

    // convT3: G2 [64][64] s2 p1 k4 -> G3 [32][128].  2o x 8t, f32x2
    {
        const int oo = (tid & 15) * 2;
        const int tt0 = (tid >> 4) * 8;
        u64 ap[8];
        if (tid < 32) BS[tid] = db3[tid];
        __syncthreads();
        {
            u64 bb = pk2(BS[oo], BS[oo + 1]);
            #pragma unroll
            for (int t = 0; t < 8; t++) ap[t] = bb;
        }
        #pragma unroll
        for (int ch = 0; ch < 2; ch++) {
            __syncthreads();
            const float4* src = (const float4*)(g_wt + GW_DW3T + ch * 4352);
            for (int i = tid; i < 1088; i += 256) ((float4*)WT)[i] = src[i];
            __syncthreads();
            for (int cl = 0; cl < 32; cl++) {
                const float* xr = &G2[(ch * 32 + cl) * 68 + (tt0 >> 1)];
                float4 v = *(const float4*)xr;
                float2 v2 = *(const float2*)(xr + 4);
                u64 xp[6];
                xp[0]=pk(v.x); xp[1]=pk(v.y); xp[2]=pk(v.z); xp[3]=pk(v.w);
                xp[4]=pk(v2.x); xp[5]=pk(v2.y);
                const float* wb = &WT[(cl * 4) * 34 + oo];
                u64 w0 = *(const u64*)(wb);
                u64 w1 = *(const u64*)(wb + 34);
                u64 w2 = *(const u64*)(wb + 68);
                u64 w3 = *(const u64*)(wb + 102);
                #pragma unroll
                for (int t = 0; t < 8; t++) {
                    int u1 = ((t + 1) >> 1) + 1;
                    if (t & 1) {
                        fma2(ap[t], w0, xp[u1]);
                        fma2(ap[t], w2, xp[u1 - 1]);
                    } else {
                        fma2(ap[t], w1, xp[u1]);
                        fma2(ap[t], w3, xp[u1 - 1]);
                    }
                }
            }
        }
        __syncthreads();
        #pragma unroll
        for (int t = 0; t < 8; t++) {
            float2 p = upk(ap[t]);
            G3[oo * 132 + tt0 + t]       = p.x;
            G3[(oo + 1) * 132 + tt0 + t] = p.y;
        }
    }
    __syncthreads();

    // final GEMM: logits[l][v] = sum_e G3[e][l] * ow[v*32+e] + ob[v].  4v x 8l x2, f32x2
    {
        const float4* src = (const float4*)(g_wt + GW_OWT);
        for (int i = tid; i < 1056; i += 256) ((float4*)WT)[i] = src[i];
        if (tid < 128) OB[tid] = ob[tid];
        __syncthreads();
        const int v0 = (tid & 31) * 4;
        const int l0 = (tid >> 5) * 16;
        #pragma unroll
        for (int lh = 0; lh < 2; lh++) {
            const int l = l0 + lh * 8;
            u64 g01[8], g23[8];
            {
                u64 b01 = pk2(OB[v0], OB[v0 + 1]);
                u64 b23 = pk2(OB[v0 + 2], OB[v0 + 3]);
                #pragma unroll
                for (int u = 0; u < 8; u++) { g01[u] = b01; g23[u] = b23; }
            }
            for (int e = 0; e < 32; e++) {
                const float* xr = &G3[e * 132 + l];
                float4 va = *(const float4*)xr;
                float4 vb = *(const float4*)(xr + 4);
                u64 xp[8];
                xp[0]=pk(va.x); xp[1]=pk(va.y); xp[2]=pk(va.z); xp[3]=pk(va.w);
                xp[4]=pk(vb.x); xp[5]=pk(vb.y); xp[6]=pk(vb.z); xp[7]=pk(vb.w);
                const u64* wp = (const u64*)&WT[e * 132 + v0];
                u64 w01 = wp[0], w23 = wp[1];
                #pragma unroll
                for (int u = 0; u < 8; u++) {
                    fma2(g01[u], w01, xp[u]);
                    fma2(g23[u], w23, xp[u]);
                }
            }
            float* outp = out_logits + ((size_t)b * 128 + l) * 128 + v0;
            #pragma unroll
            for (int u = 0; u < 8; u++) {
                float2 p01 = upk(g01[u]), p23 = upk(g23[u]);
                float4 vv = make_float4(p01.x, p01.y, p23.x, p23.y);
                __stcs((float4*)(outp + (size_t)u * 128), vv);
            }
        }
    }
}

// Deterministic loss reduce
__global__ void loss_kernel(float* __restrict__ out_loss)
{
    __shared__ float sm[256];
    float a = 0.f;
    for (int i = threadIdx.x; i < BB; i += 256) a += g_partial[i];
    sm[threadIdx.x] = a;
    __syncthreads();
    for (int sft = 128; sft > 0; sft >>= 1) {
        if (threadIdx.x < sft) sm[threadIdx.x] += sm[threadIdx.x + sft];
        __syncthreads();
    }
    if (threadIdx.x == 0)
        out_loss[0] = sm[0] * (1.25f / (2048.f * 30.f * 64.f));
}

extern "C" void kernel_launch(void* const* d_in, const int* in_sizes, int n_in,
                              void* d_out, int out_size)
{
    const int*   ti     = (const int*)  d_in[0];
    const float* emb    = (const float*)d_in[1];
    const float* enc_w1 = (const float*)d_in[2];
    const float* enc_b1 = (const float*)d_in[3];
    const float* enc_w2 = (const float*)d_in[4];
    const float* enc_b2 = (const float*)d_in[5];
    const float* enc_w3 = (const float*)d_in[6];
    const float* enc_b3 = (const float*)d_in[7];
    const float* cb     = (const float*)d_in[8];
    const float* dec_w1 = (const float*)d_in[9];
    const float* dec_b1 = (const float*)d_in[10];
    const float* dec_w2 = (const float*)d_in[11];
    const float* dec_b2 = (const float*)d_in[12];
    const float* dec_w3 = (const float*)d_in[13];
    const float* dec_b3 = (const float*)d_in[14];
    const float* out_w  = (const float*)d_in[15];
    const float* out_b  = (const float*)d_in[16];

    float* out        = (float*)d_out;
    float* out_logits = out;
    float* out_puzz   = out + OFF_PUZZ;
    float* out_feat   = out + OFF_FEAT;
    float* out_qst    = out + OFF_QST;
    float* out_loss   = out + OFF_LOSS;

    cudaFuncSetAttribute(fused_kernel, cudaFuncAttributeMaxDynamicSharedMemorySize, SM_BYTES);

    prep_kernel<<<64, 256>>>(enc_w1, enc_w2, enc_w3, dec_w1, dec_w2, dec_w3, out_w);
    fused_kernel<<<BB, 256, SM_BYTES>>>(ti, emb, enc_b1, enc_b2, enc_b3, cb,
                                        dec_b1, dec_b2, dec_b3, out_b,
                                        out_logits, out_feat, out_qst, out_puzz);
    loss_kernel<<<1, 256>>>(out_loss);
}